// round 14
// baseline (speedup 1.0000x reference)
#include <cuda_runtime.h>
#include <cuda_fp16.h>
#include <cstdint>

#define M_NODES 1024
#define NTH 512
#define TJ 512
#define NBLK 148
#define TS36 36   // Ts row stride in u32 (32 data + 4 pad -> conflict-free)

// scratch (no cudaMalloc allowed)
__device__ float g_Pi[M_NODES * 64];
__device__ __align__(16) __half g_Pjh[M_NODES * 64];

// ---- half2 helpers --------------------------------------------------------
__device__ __forceinline__ uint32_t packh2(float lo, float hi) {
    uint32_t r;
    asm("cvt.rn.f16x2.f32 %0, %1, %2;" : "=r"(r) : "f"(hi), "f"(lo));
    return r;
}
__device__ __forceinline__ float2 uph2(uint32_t v) {
    __half2 h; *(uint32_t*)&h = v;
    return __half22float2(h);
}
__device__ __forceinline__ uint32_t hfma2v(uint32_t a, uint32_t b, uint32_t c) {
    uint32_t d;
    asm("fma.rn.f16x2 %0, %1, %2, %3;" : "=r"(d) : "r"(a), "r"(b), "r"(c));
    return d;
}
__device__ __forceinline__ uint32_t hadd2v(uint32_t a, uint32_t b) {
    uint32_t d;
    asm("add.rn.f16x2 %0, %1, %2;" : "=r"(d) : "r"(a), "r"(b));
    return d;
}
// silu on a packed half2: hx = 0.5*p; t = tanh(hx); res = hx*t + hx
__device__ __forceinline__ uint32_t silu2h(uint32_t p2) {
    uint32_t hx, t;
    const uint32_t H05 = 0x38003800u;  // half2(0.5, 0.5)
    asm("mul.rn.f16x2 %0, %1, %2;" : "=r"(hx) : "r"(p2), "r"(H05));
    asm("tanh.approx.f16x2 %0, %1;" : "=r"(t) : "r"(hx));
    return hfma2v(hx, t, hx);
}
__device__ __forceinline__ float silu_t(float v) {
    float hx = 0.5f * v;
    float t;
    asm("tanh.approx.f32 %0, %1;" : "=f"(t) : "f"(hx));
    return fmaf(hx, t, hx);
}

__device__ __forceinline__ void mma16(float* c, const uint32_t* a, const uint32_t* b) {
    asm volatile(
        "mma.sync.aligned.m16n8k16.row.col.f32.f16.f16.f32 "
        "{%0,%1,%2,%3}, {%4,%5,%6,%7}, {%8,%9}, {%0,%1,%2,%3};"
        : "+f"(c[0]), "+f"(c[1]), "+f"(c[2]), "+f"(c[3])
        : "r"(a[0]), "r"(a[1]), "r"(a[2]), "r"(a[3]), "r"(b[0]), "r"(b[1]));
}
__device__ __forceinline__ void ldsm4(uint32_t* r, uint32_t addr) {
    asm volatile("ldmatrix.sync.aligned.m8n8.x4.shared.b16 {%0,%1,%2,%3}, [%4];"
        : "=r"(r[0]), "=r"(r[1]), "=r"(r[2]), "=r"(r[3]) : "r"(addr));
}

// ---------------------------------------------------------------------------
__global__ void prep_kernel(const float* __restrict__ h,
                            const float* __restrict__ We1,
                            const float* __restrict__ be1) {
    int idx = blockIdx.x * blockDim.x + threadIdx.x;
    int i = idx >> 6, c = idx & 63;
    const float* hr = h + i * 64;
    float pi = be1[c], pj = 0.f;
#pragma unroll 16
    for (int k = 0; k < 64; k++) {
        float hv = hr[k];
        pi = fmaf(hv, We1[k * 64 + c], pi);
        pj = fmaf(hv, We1[(64 + k) * 64 + c], pj);
    }
    g_Pi[idx] = pi;
    g_Pjh[idx] = __float2half(pj);
}

// ---------------------------------------------------------------------------
// Warp-GEMM (fp16 m16n8k16): A via ldmatrix.x4 from Ts (row stride 144B),
// B from fragment-ordered half weights Wf, bias fragment-ordered.
// ---------------------------------------------------------------------------
__device__ __forceinline__ void do_gemm(const uint32_t* __restrict__ Wf,
                                        const float* __restrict__ biasf,
                                        float acc[2][8][4],
                                        uint32_t a_addr, int t4, int lane) {
    const float4* bf = (const float4*)(biasf + t4 * 16);
#pragma unroll
    for (int np = 0; np < 4; np++) {
        float4 b = bf[np];
#pragma unroll
        for (int mt = 0; mt < 2; mt++) {
            acc[mt][2*np][0] = b.x; acc[mt][2*np][1] = b.y;
            acc[mt][2*np][2] = b.x; acc[mt][2*np][3] = b.y;
            acc[mt][2*np+1][0] = b.z; acc[mt][2*np+1][1] = b.w;
            acc[mt][2*np+1][2] = b.z; acc[mt][2*np+1][3] = b.w;
        }
    }
#pragma unroll
    for (int kt = 0; kt < 4; kt++) {
        uint32_t A0[4], A1[4];
        ldsm4(A0, a_addr + kt * 32);
        ldsm4(A1, a_addr + 16 * 144 + kt * 32);
#pragma unroll
        for (int np = 0; np < 4; np++) {
            uint4 Bv = ((const uint4*)Wf)[(kt * 4 + np) * 32 + lane];
            uint32_t B0[2] = {Bv.x, Bv.y};
            uint32_t B1[2] = {Bv.z, Bv.w};
            mma16(acc[0][2*np],   A0, B0);
            mma16(acc[1][2*np],   A1, B0);
            mma16(acc[0][2*np+1], A0, B1);
            mma16(acc[1][2*np+1], A1, B1);
        }
    }
}

// ---------------------------------------------------------------------------
// Persistent fused kernel (R7 structure): 148 CTAs x 512 threads (16 warps).
// Phase1 computed in packed f16x2 (g_Pj stored fp16); Wh1/Wh2 staged in SMEM.
// ---------------------------------------------------------------------------
// SMEM (u32 words):
// Ts 18432 | Wf2 2048 | Wf1 2048 | xs 3072 | Wh1s 8192 | Wh2s 4096 | fm 2192
#define SM_TS  0
#define SM_WF2 18432
#define SM_WF1 20480
#define SM_XS  22528
#define SM_WH1 25600
#define SM_WH2 33792
#define SM_FM  37888
#define SM_TOTAL 40080
#define SMEM_BYTES (SM_TOTAL * 4)

__global__ void __launch_bounds__(NTH, 1)
ecnn_main(const float* __restrict__ x, const float* __restrict__ a,
          const float* __restrict__ h, const float* __restrict__ We1,
          const float* __restrict__ We2, const float* __restrict__ be2,
          const float* __restrict__ Wx1, const float* __restrict__ bx1,
          const float* __restrict__ Wx2, const float* __restrict__ bx2,
          const float* __restrict__ Wh1, const float* __restrict__ bh1,
          const float* __restrict__ Wh2, const float* __restrict__ bh2,
          float* __restrict__ out) {
    extern __shared__ uint32_t sm[];
    uint32_t* Ts   = sm + SM_TS;
    uint32_t* Wf2  = sm + SM_WF2;
    uint32_t* Wf1  = sm + SM_WF1;
    float*    xs   = (float*)(sm + SM_XS);
    float*    Wh1s = (float*)(sm + SM_WH1);
    float*    Wh2s = (float*)(sm + SM_WH2);
    float*    fm   = (float*)(sm + SM_FM);
    float*    biasf2 = fm;           // 64
    float*    biasf1 = fm + 64;      // 64
    float*    wx2f   = fm + 128;     // 64
    uint32_t* wdh    = (uint32_t*)(fm + 192);  // 32
    uint32_t* wah    = (uint32_t*)(fm + 224);  // 32
    uint32_t* Pih    = (uint32_t*)(fm + 256);  // 32
    float*    s_sh   = fm + 288;     // 512
    float*    mired  = fm + 800;     // 1024
    float*    mi_s   = fm + 1824;    // 64
    float*    hids   = fm + 1888;    // 64
    float*    xred   = fm + 1952;    // 48
    float*    bh1s   = fm + 2000;    // 64
    float*    bh2s   = fm + 2064;    // 64
    float*    his    = fm + 2128;    // 64

    const int tid  = threadIdx.x;
    const int lane = tid & 31;
    const int warp = tid >> 5;
    const int wrow = warp << 5;
    const int g    = lane >> 2;
    const int t4   = lane & 3;

    // ldmatrix source address (lane-fixed): rows of this warp's A tile
    const int lrow = (lane & 7) + ((lane >> 3) & 1) * 8;
    const uint32_t ts_sh = (uint32_t)__cvta_generic_to_shared(Ts);
    const uint32_t a_addr = ts_sh + (uint32_t)(wrow + lrow) * 144u
                                  + (uint32_t)((lane >> 4) & 1) * 16u;

    // ---- one-time staging (persistent CTA) ----
    for (int idx = tid; idx < 4096; idx += NTH) {
        int k = idx >> 6, n = idx & 63;
        int kt = k >> 4, tt = (k >> 1) & 3, hi = (k >> 3) & 1, lo = k & 1;
        int np = n >> 4, s2 = (n >> 3) & 1, gg = n & 7;
        int dst = (((kt * 4 + np) * 32 + (gg * 4 + tt)) * 4 + s2 * 2 + hi) * 2 + lo;
        ((__half*)Wf2)[dst] = __float2half(We2[idx]);
        ((__half*)Wf1)[dst] = __float2half(Wx1[idx]);
    }
    for (int idx = tid; idx < 3072; idx += NTH) xs[idx] = x[idx];
    for (int idx = tid; idx < 8192; idx += NTH) Wh1s[idx] = Wh1[idx];
    for (int idx = tid; idx < 4096; idx += NTH) Wh2s[idx] = Wh2[idx];
    if (tid < 64) {
        int nt = tid >> 3, u = tid & 7;
        int dst = (u >> 1) * 16 + nt * 2 + (u & 1);
        biasf2[dst] = be2[tid];
        biasf1[dst] = bx1[tid];
        wx2f[dst]   = Wx2[tid];
        bh1s[tid]   = bh1[tid];
        bh2s[tid]   = bh2[tid];
    }
    if (tid < 32) {
        wdh[tid] = packh2(We1[128 * 64 + 2 * tid], We1[128 * 64 + 2 * tid + 1]);
        wah[tid] = packh2(We1[129 * 64 + 2 * tid], We1[129 * 64 + 2 * tid + 1]);
    }
    __syncthreads();

    // pack wx2 fragment into half2 registers (loop-invariant)
    uint32_t wxh[4][2];
    {
        const float4* wxf = (const float4*)(wx2f + t4 * 16);
#pragma unroll
        for (int np = 0; np < 4; np++) {
            float4 w = wxf[np];
            wxh[np][0] = packh2(w.x, w.y);
            wxh[np][1] = packh2(w.z, w.w);
        }
    }

    const float bx2v = bx2[0];
    const float C = 1.0f / (float)(M_NODES - 1);

    for (int i = blockIdx.x; i < M_NODES; i += NBLK) {
        const float* arow = a + (size_t)i * M_NODES;
        const float aij0 = arow[tid];
        const float aij1 = arow[TJ + tid];

        __syncthreads();   // s_sh/Pih/mired/his reuse from previous i
        if (tid < 32) {
            Pih[tid] = packh2(g_Pi[i * 64 + 2 * tid], g_Pi[i * 64 + 2 * tid + 1]);
        } else if (tid < 96) {
            his[tid - 32] = h[i * 64 + tid - 32];
        }
        __syncthreads();

        const float xi0 = xs[i * 3 + 0];
        const float xi1 = xs[i * 3 + 1];
        const float xi2 = xs[i * 3 + 2];

        float macc[16];
#pragma unroll
        for (int q = 0; q < 16; q++) macc[q] = 0.f;
        float xa0 = 0.f, xa1 = 0.f, xa2 = 0.f;

#pragma unroll
        for (int jb = 0; jb < M_NODES; jb += TJ) {
            __syncwarp();   // Ts/s_sh reuse (warp-local rows)
            const int j = jb + tid;
            const float dx0 = xi0 - xs[j * 3 + 0];
            const float dx1 = xi1 - xs[j * 3 + 1];
            const float dx2 = xi2 - xs[j * 3 + 2];
            const float d2  = dx0 * dx0 + dx1 * dx1 + dx2 * dx2;
            const float aij = (jb == 0) ? aij0 : aij1;
            const uint32_t d2h  = packh2(d2, d2);
            const uint32_t aijh = packh2(aij, aij);

            // ---- phase 1: t = silu(pre) fully in f16x2 -> Ts ----
            const uint4* pjr = (const uint4*)(g_Pjh + j * 64);
            uint4* trow = (uint4*)(Ts + tid * TS36);
#pragma unroll
            for (int k8 = 0; k8 < 8; k8++) {
                uint4 pj = pjr[k8];
                uint4 pi = *(const uint4*)&Pih[k8 * 4];
                uint4 wd = *(const uint4*)&wdh[k8 * 4];
                uint4 wa = *(const uint4*)&wah[k8 * 4];
                uint4 o;
                o.x = silu2h(hfma2v(aijh, wa.x, hfma2v(d2h, wd.x, hadd2v(pi.x, pj.x))));
                o.y = silu2h(hfma2v(aijh, wa.y, hfma2v(d2h, wd.y, hadd2v(pi.y, pj.y))));
                o.z = silu2h(hfma2v(aijh, wa.z, hfma2v(d2h, wd.z, hadd2v(pi.z, pj.z))));
                o.w = silu2h(hfma2v(aijh, wa.w, hfma2v(d2h, wd.w, hadd2v(pi.w, pj.w))));
                trow[k8] = o;
            }
            __syncwarp();

            // ---- gemm1: m_pre = T @ We2 + be2 ----
            float acc[2][8][4];
            do_gemm(Wf2, biasf2, acc, a_addr, t4, lane);
            __syncwarp();

            // ---- epilogue1: m = silu (half2); macc (f32); Ts <- m ----
#pragma unroll
            for (int mt = 0; mt < 2; mt++) {
                const int e0 = wrow + mt * 16 + g;
                const int e1 = e0 + 8;
                const bool d0 = (jb + e0) == i;
                const bool d1 = (jb + e1) == i;
#pragma unroll
                for (int nt = 0; nt < 8; nt++) {
                    uint32_t h0 = silu2h(packh2(acc[mt][nt][0], acc[mt][nt][1]));
                    uint32_t h1 = silu2h(packh2(acc[mt][nt][2], acc[mt][nt][3]));
                    float2 f0 = uph2(h0);
                    float2 f1 = uph2(h1);
                    if (!d0) { macc[nt*2] += f0.x; macc[nt*2+1] += f0.y; }
                    if (!d1) { macc[nt*2] += f1.x; macc[nt*2+1] += f1.y; }
                    Ts[e0 * TS36 + nt * 4 + t4] = h0;
                    Ts[e1 * TS36 + nt * 4 + t4] = h1;
                }
            }
            __syncwarp();

            // ---- gemm2: u_pre = M @ Wx1 + bx1 ----
            do_gemm(Wf1, biasf1, acc, a_addr, t4, lane);

            // ---- epilogue2: s = silu(u) . Wx2 + bx2 (half2 dot) ----
            uint32_t se0a = 0, se1a = 0, se0b = 0, se1b = 0;
#pragma unroll
            for (int np = 0; np < 4; np++) {
#pragma unroll
                for (int mt = 0; mt < 2; mt++) {
                    uint32_t u01e0 = silu2h(packh2(acc[mt][2*np][0],   acc[mt][2*np][1]));
                    uint32_t u01e1 = silu2h(packh2(acc[mt][2*np][2],   acc[mt][2*np][3]));
                    uint32_t u23e0 = silu2h(packh2(acc[mt][2*np+1][0], acc[mt][2*np+1][1]));
                    uint32_t u23e1 = silu2h(packh2(acc[mt][2*np+1][2], acc[mt][2*np+1][3]));
                    if (mt == 0) {
                        se0a = hfma2v(u01e0, wxh[np][0], se0a);
                        se0a = hfma2v(u23e0, wxh[np][1], se0a);
                        se1a = hfma2v(u01e1, wxh[np][0], se1a);
                        se1a = hfma2v(u23e1, wxh[np][1], se1a);
                    } else {
                        se0b = hfma2v(u01e0, wxh[np][0], se0b);
                        se0b = hfma2v(u23e0, wxh[np][1], se0b);
                        se1b = hfma2v(u01e1, wxh[np][0], se1b);
                        se1b = hfma2v(u23e1, wxh[np][1], se1b);
                    }
                }
            }
            float2 fr;
            fr = uph2(se0a); float sp0 = fr.x + fr.y;
            fr = uph2(se1a); float sp1 = fr.x + fr.y;
            fr = uph2(se0b); float sp2 = fr.x + fr.y;
            fr = uph2(se1b); float sp3 = fr.x + fr.y;

            sp0 += __shfl_xor_sync(0xffffffffu, sp0, 1);
            sp0 += __shfl_xor_sync(0xffffffffu, sp0, 2);
            sp1 += __shfl_xor_sync(0xffffffffu, sp1, 1);
            sp1 += __shfl_xor_sync(0xffffffffu, sp1, 2);
            sp2 += __shfl_xor_sync(0xffffffffu, sp2, 1);
            sp2 += __shfl_xor_sync(0xffffffffu, sp2, 2);
            sp3 += __shfl_xor_sync(0xffffffffu, sp3, 1);
            sp3 += __shfl_xor_sync(0xffffffffu, sp3, 2);
            if (t4 == 0) {
                s_sh[wrow + g]      = sp0 + bx2v;
                s_sh[wrow + 8 + g]  = sp1 + bx2v;
                s_sh[wrow + 16 + g] = sp2 + bx2v;
                s_sh[wrow + 24 + g] = sp3 + bx2v;
            }
            __syncwarp();

            // ---- phase 4: coordinate accumulation ----
            float s = s_sh[tid];
            if (j != i) {
                xa0 = fmaf(dx0, s, xa0);
                xa1 = fmaf(dx1, s, xa1);
                xa2 = fmaf(dx2, s, xa2);
            }
        }

        // ---- macc: reduce over g within warp, write per-warp partials ----
#pragma unroll
        for (int q = 0; q < 16; q++) {
            macc[q] += __shfl_xor_sync(0xffffffffu, macc[q], 4);
            macc[q] += __shfl_xor_sync(0xffffffffu, macc[q], 8);
            macc[q] += __shfl_xor_sync(0xffffffffu, macc[q], 16);
        }
        if (lane < 4) {
#pragma unroll
            for (int nt = 0; nt < 8; nt++) {
                mired[warp * 64 + nt * 8 + lane * 2]     = macc[nt * 2];
                mired[warp * 64 + nt * 8 + lane * 2 + 1] = macc[nt * 2 + 1];
            }
        }
#pragma unroll
        for (int o = 16; o >= 1; o >>= 1) {
            xa0 += __shfl_xor_sync(0xffffffffu, xa0, o);
            xa1 += __shfl_xor_sync(0xffffffffu, xa1, o);
            xa2 += __shfl_xor_sync(0xffffffffu, xa2, o);
        }
        if (lane == 0) {
            xred[warp * 3 + 0] = xa0;
            xred[warp * 3 + 1] = xa1;
            xred[warp * 3 + 2] = xa2;
        }
        __syncthreads();

        if (tid < 64) {
            float s = 0.f;
#pragma unroll
            for (int w = 0; w < 16; w++) s += mired[w * 64 + tid];
            mi_s[tid] = s;
        }
        if (tid < 3) {
            float s = 0.f;
#pragma unroll
            for (int w = 0; w < 16; w++) s += xred[w * 3 + tid];
            out[i * 3 + tid] = fmaf(C, s, xs[i * 3 + tid]);
        }
        __syncthreads();

        // ---- h_new: 2-layer MLP (weights from SMEM) ----
        if (tid < 256) {
            const int c = tid & 63, p = tid >> 6;
            float a1 = 0.f;
            if (p < 2) {
                const float* hr = his + p * 32;
                const float* wr = Wh1s + (p * 32) * 64 + c;
#pragma unroll 8
                for (int q = 0; q < 32; q++) a1 = fmaf(hr[q], wr[q * 64], a1);
            } else {
                const float* mr = mi_s + (p - 2) * 32;
                const float* wr = Wh1s + (64 + (p - 2) * 32) * 64 + c;
#pragma unroll 8
                for (int q = 0; q < 32; q++) a1 = fmaf(mr[q], wr[q * 64], a1);
            }
            s_sh[tid] = a1;
        }
        __syncthreads();
        if (tid < 64)
            hids[tid] = silu_t(bh1s[tid] + s_sh[tid] + s_sh[64 + tid] +
                               s_sh[128 + tid] + s_sh[192 + tid]);
        __syncthreads();
        if (tid < 256) {
            const int c = tid & 63, p = tid >> 6;
            float a2 = 0.f;
            const float* hp = hids + p * 16;
            const float* wr = Wh2s + (p * 16) * 64 + c;
#pragma unroll 8
            for (int q = 0; q < 16; q++) a2 = fmaf(hp[q], wr[q * 64], a2);
            s_sh[tid] = a2;
        }
        __syncthreads();
        if (tid < 64)
            out[3 * M_NODES + i * 64 + tid] =
                bh2s[tid] + s_sh[tid] + s_sh[64 + tid] + s_sh[128 + tid] + s_sh[192 + tid];
    }
}

extern "C" void kernel_launch(void* const* d_in, const int* in_sizes, int n_in,
                              void* d_out, int out_size) {
    const float* x   = (const float*)d_in[0];
    const float* a   = (const float*)d_in[1];
    const float* h   = (const float*)d_in[2];
    const float* We1 = (const float*)d_in[3];
    const float* be1 = (const float*)d_in[4];
    const float* We2 = (const float*)d_in[5];
    const float* be2 = (const float*)d_in[6];
    const float* Wx1 = (const float*)d_in[7];
    const float* bx1 = (const float*)d_in[8];
    const float* Wx2 = (const float*)d_in[9];
    const float* bx2 = (const float*)d_in[10];
    const float* Wh1 = (const float*)d_in[11];
    const float* bh1 = (const float*)d_in[12];
    const float* Wh2 = (const float*)d_in[13];
    const float* bh2 = (const float*)d_in[14];
    float* out = (float*)d_out;

    cudaFuncSetAttribute(ecnn_main, cudaFuncAttributeMaxDynamicSharedMemorySize,
                         SMEM_BYTES);

    prep_kernel<<<(M_NODES * 64) / 256, 256>>>(h, We1, be1);
    ecnn_main<<<NBLK, NTH, SMEM_BYTES>>>(
        x, a, h, We1, We2, be2, Wx1, bx1, Wx2, bx2, Wh1, bh1, Wh2, bh2, out);
}

// round 17
// speedup vs baseline: 1.0540x; 1.0540x over previous
#include <cuda_runtime.h>
#include <cuda_fp16.h>
#include <cstdint>

#define M_NODES 1024
#define NTH 512
#define TJ 512
#define NBLK 148
#define TS36 36   // Ts row stride in u32 (32 data + 4 pad -> conflict-free)

// scratch (no cudaMalloc allowed)
__device__ float g_Pi[M_NODES * 64];
__device__ __align__(16) __half g_Pjh[M_NODES * 64];

// ---- half2 helpers --------------------------------------------------------
__device__ __forceinline__ uint32_t packh2(float lo, float hi) {
    uint32_t r;
    asm("cvt.rn.f16x2.f32 %0, %1, %2;" : "=r"(r) : "f"(hi), "f"(lo));
    return r;
}
__device__ __forceinline__ float2 uph2(uint32_t v) {
    __half2 h; *(uint32_t*)&h = v;
    return __half22float2(h);
}
__device__ __forceinline__ uint32_t hfma2v(uint32_t a, uint32_t b, uint32_t c) {
    uint32_t d;
    asm("fma.rn.f16x2 %0, %1, %2, %3;" : "=r"(d) : "r"(a), "r"(b), "r"(c));
    return d;
}
__device__ __forceinline__ uint32_t hadd2v(uint32_t a, uint32_t b) {
    uint32_t d;
    asm("add.rn.f16x2 %0, %1, %2;" : "=r"(d) : "r"(a), "r"(b));
    return d;
}
// silu on a packed half2: hx = 0.5*p; t = tanh(hx); res = hx*t + hx
__device__ __forceinline__ uint32_t silu2h(uint32_t p2) {
    uint32_t hx, t;
    const uint32_t H05 = 0x38003800u;  // half2(0.5, 0.5)
    asm("mul.rn.f16x2 %0, %1, %2;" : "=r"(hx) : "r"(p2), "r"(H05));
    asm("tanh.approx.f16x2 %0, %1;" : "=r"(t) : "r"(hx));
    return hfma2v(hx, t, hx);
}
__device__ __forceinline__ float silu_t(float v) {
    float hx = 0.5f * v;
    float t;
    asm("tanh.approx.f32 %0, %1;" : "=f"(t) : "f"(hx));
    return fmaf(hx, t, hx);
}

// fp16-accumulate MMA: D,C packed half2 (2 regs)
__device__ __forceinline__ void mma16h(uint32_t* c, const uint32_t* a, const uint32_t* b) {
    asm volatile(
        "mma.sync.aligned.m16n8k16.row.col.f16.f16.f16.f16 "
        "{%0,%1}, {%2,%3,%4,%5}, {%6,%7}, {%0,%1};"
        : "+r"(c[0]), "+r"(c[1])
        : "r"(a[0]), "r"(a[1]), "r"(a[2]), "r"(a[3]), "r"(b[0]), "r"(b[1]));
}
__device__ __forceinline__ void ldsm4(uint32_t* r, uint32_t addr) {
    asm volatile("ldmatrix.sync.aligned.m8n8.x4.shared.b16 {%0,%1,%2,%3}, [%4];"
        : "=r"(r[0]), "=r"(r[1]), "=r"(r[2]), "=r"(r[3]) : "r"(addr));
}

// ---------------------------------------------------------------------------
__global__ void prep_kernel(const float* __restrict__ h,
                            const float* __restrict__ We1,
                            const float* __restrict__ be1) {
    int idx = blockIdx.x * blockDim.x + threadIdx.x;
    int i = idx >> 6, c = idx & 63;
    const float* hr = h + i * 64;
    float pi = be1[c], pj = 0.f;
#pragma unroll 16
    for (int k = 0; k < 64; k++) {
        float hv = hr[k];
        pi = fmaf(hv, We1[k * 64 + c], pi);
        pj = fmaf(hv, We1[(64 + k) * 64 + c], pj);
    }
    g_Pi[idx] = pi;
    g_Pjh[idx] = __float2half(pj);
}

// ---------------------------------------------------------------------------
// Warp-GEMM (fp16 in / fp16 accum): A via ldmatrix.x4 from Ts (stride 144B),
// B fragment-ordered; bias pre-packed half2 fragments folded into C.
// acc[mt][nt][r]: r=0 -> row g, r=1 -> row g+8, cols {nt*8+2*t4, +1} (packed).
// ---------------------------------------------------------------------------
__device__ __forceinline__ void do_gemm(const uint32_t* __restrict__ Wf,
                                        const uint32_t* __restrict__ biash,
                                        uint32_t acc[2][8][2],
                                        uint32_t a_addr, int t4, int lane) {
    const uint4* bh = (const uint4*)(biash + t4 * 8);
    uint4 b0 = bh[0], b1 = bh[1];
#pragma unroll
    for (int mt = 0; mt < 2; mt++) {
        acc[mt][0][0] = b0.x; acc[mt][0][1] = b0.x;
        acc[mt][1][0] = b0.y; acc[mt][1][1] = b0.y;
        acc[mt][2][0] = b0.z; acc[mt][2][1] = b0.z;
        acc[mt][3][0] = b0.w; acc[mt][3][1] = b0.w;
        acc[mt][4][0] = b1.x; acc[mt][4][1] = b1.x;
        acc[mt][5][0] = b1.y; acc[mt][5][1] = b1.y;
        acc[mt][6][0] = b1.z; acc[mt][6][1] = b1.z;
        acc[mt][7][0] = b1.w; acc[mt][7][1] = b1.w;
    }
#pragma unroll
    for (int kt = 0; kt < 4; kt++) {
        uint32_t A0[4], A1[4];
        ldsm4(A0, a_addr + kt * 32);
        ldsm4(A1, a_addr + 16 * 144 + kt * 32);
#pragma unroll
        for (int np = 0; np < 4; np++) {
            uint4 Bv = ((const uint4*)Wf)[(kt * 4 + np) * 32 + lane];
            uint32_t B0[2] = {Bv.x, Bv.y};
            uint32_t B1[2] = {Bv.z, Bv.w};
            mma16h(acc[0][2*np],   A0, B0);
            mma16h(acc[1][2*np],   A1, B0);
            mma16h(acc[0][2*np+1], A0, B1);
            mma16h(acc[1][2*np+1], A1, B1);
        }
    }
}

// ---------------------------------------------------------------------------
// Persistent fused kernel: 148 CTAs x 512 threads (16 warps), fp16-accum MMA.
// ---------------------------------------------------------------------------
#define SM_TS  0
#define SM_WF2 18432
#define SM_WF1 20480
#define SM_XS  22528
#define SM_WH1 25600
#define SM_WH2 33792
#define SM_FM  37888
#define SM_TOTAL 40080
#define SMEM_BYTES (SM_TOTAL * 4)

__global__ void __launch_bounds__(NTH, 1)
ecnn_main(const float* __restrict__ x, const float* __restrict__ a,
          const float* __restrict__ h, const float* __restrict__ We1,
          const float* __restrict__ We2, const float* __restrict__ be2,
          const float* __restrict__ Wx1, const float* __restrict__ bx1,
          const float* __restrict__ Wx2, const float* __restrict__ bx2,
          const float* __restrict__ Wh1, const float* __restrict__ bh1,
          const float* __restrict__ Wh2, const float* __restrict__ bh2,
          float* __restrict__ out) {
    extern __shared__ uint32_t sm[];
    uint32_t* Ts   = sm + SM_TS;
    uint32_t* Wf2  = sm + SM_WF2;
    uint32_t* Wf1  = sm + SM_WF1;
    float*    xs   = (float*)(sm + SM_XS);
    float*    Wh1s = (float*)(sm + SM_WH1);
    float*    Wh2s = (float*)(sm + SM_WH2);
    float*    fm   = (float*)(sm + SM_FM);
    uint32_t* biash2 = (uint32_t*)fm;            // 32
    uint32_t* biash1 = (uint32_t*)(fm + 32);     // 32
    float*    wx2f   = fm + 64;                  // 64
    uint32_t* wdh    = (uint32_t*)(fm + 128);    // 32
    uint32_t* wah    = (uint32_t*)(fm + 160);    // 32
    uint32_t* Pih    = (uint32_t*)(fm + 192);    // 32
    float*    s_sh   = fm + 224;                 // 512
    float*    mired  = fm + 736;                 // 1024
    float*    mi_s   = fm + 1760;                // 64
    float*    hids   = fm + 1824;                // 64
    float*    xred   = fm + 1888;                // 48
    float*    bh1s   = fm + 1936;                // 64
    float*    bh2s   = fm + 2000;                // 64
    float*    his    = fm + 2064;                // 64

    const int tid  = threadIdx.x;
    const int lane = tid & 31;
    const int warp = tid >> 5;
    const int wrow = warp << 5;
    const int g    = lane >> 2;
    const int t4   = lane & 3;

    const int lrow = (lane & 7) + ((lane >> 3) & 1) * 8;
    const uint32_t ts_sh = (uint32_t)__cvta_generic_to_shared(Ts);
    const uint32_t a_addr = ts_sh + (uint32_t)(wrow + lrow) * 144u
                                  + (uint32_t)((lane >> 4) & 1) * 16u;

    // ---- one-time staging (persistent CTA) ----
    for (int idx = tid; idx < 4096; idx += NTH) {
        int k = idx >> 6, n = idx & 63;
        int kt = k >> 4, tt = (k >> 1) & 3, hi = (k >> 3) & 1, lo = k & 1;
        int np = n >> 4, s2 = (n >> 3) & 1, gg = n & 7;
        int dst = (((kt * 4 + np) * 32 + (gg * 4 + tt)) * 4 + s2 * 2 + hi) * 2 + lo;
        ((__half*)Wf2)[dst] = __float2half(We2[idx]);
        ((__half*)Wf1)[dst] = __float2half(Wx1[idx]);
    }
    for (int idx = tid; idx < 3072; idx += NTH) xs[idx] = x[idx];
    for (int idx = tid; idx < 8192; idx += NTH) Wh1s[idx] = Wh1[idx];
    for (int idx = tid; idx < 4096; idx += NTH) Wh2s[idx] = Wh2[idx];
    if (tid < 64) {
        int nt = tid >> 3, u = tid & 7;
        int dst = (u >> 1) * 16 + nt * 2 + (u & 1);
        wx2f[dst] = Wx2[tid];
        bh1s[tid] = bh1[tid];
        bh2s[tid] = bh2[tid];
    }
    if (tid < 32) {
        int t4i = tid >> 3, nti = tid & 7;
        biash2[tid] = packh2(be2[nti * 8 + 2 * t4i], be2[nti * 8 + 2 * t4i + 1]);
        biash1[tid] = packh2(bx1[nti * 8 + 2 * t4i], bx1[nti * 8 + 2 * t4i + 1]);
        wdh[tid] = packh2(We1[128 * 64 + 2 * tid], We1[128 * 64 + 2 * tid + 1]);
        wah[tid] = packh2(We1[129 * 64 + 2 * tid], We1[129 * 64 + 2 * tid + 1]);
    }
    __syncthreads();

    // pack wx2 fragment into half2 registers (loop-invariant)
    uint32_t wxh[4][2];
    {
        const float4* wxf = (const float4*)(wx2f + t4 * 16);
#pragma unroll
        for (int np = 0; np < 4; np++) {
            float4 w = wxf[np];
            wxh[np][0] = packh2(w.x, w.y);
            wxh[np][1] = packh2(w.z, w.w);
        }
    }

    const float bx2v = bx2[0];
    const float C = 1.0f / (float)(M_NODES - 1);

    for (int i = blockIdx.x; i < M_NODES; i += NBLK) {
        const float* arow = a + (size_t)i * M_NODES;
        const float aij0 = arow[tid];
        const float aij1 = arow[TJ + tid];

        __syncthreads();   // s_sh/Pih/mired/his reuse from previous i
        if (tid < 32) {
            Pih[tid] = packh2(g_Pi[i * 64 + 2 * tid], g_Pi[i * 64 + 2 * tid + 1]);
        } else if (tid < 96) {
            his[tid - 32] = h[i * 64 + tid - 32];
        }
        __syncthreads();

        const float xi0 = xs[i * 3 + 0];
        const float xi1 = xs[i * 3 + 1];
        const float xi2 = xs[i * 3 + 2];

        float macc[16];
#pragma unroll
        for (int q = 0; q < 16; q++) macc[q] = 0.f;
        float xa0 = 0.f, xa1 = 0.f, xa2 = 0.f;

#pragma unroll
        for (int jb = 0; jb < M_NODES; jb += TJ) {
            __syncwarp();   // Ts/s_sh reuse (warp-local rows)
            const int j = jb + tid;
            const float dx0 = xi0 - xs[j * 3 + 0];
            const float dx1 = xi1 - xs[j * 3 + 1];
            const float dx2 = xi2 - xs[j * 3 + 2];
            const float d2  = dx0 * dx0 + dx1 * dx1 + dx2 * dx2;
            const float aij = (jb == 0) ? aij0 : aij1;
            const uint32_t d2h  = packh2(d2, d2);
            const uint32_t aijh = packh2(aij, aij);

            // ---- phase 1: t = silu(pre) fully in f16x2 -> Ts ----
            const uint4* pjr = (const uint4*)(g_Pjh + j * 64);
            uint4* trow = (uint4*)(Ts + tid * TS36);
#pragma unroll
            for (int k8 = 0; k8 < 8; k8++) {
                uint4 pj = pjr[k8];
                uint4 pi = *(const uint4*)&Pih[k8 * 4];
                uint4 wd = *(const uint4*)&wdh[k8 * 4];
                uint4 wa = *(const uint4*)&wah[k8 * 4];
                uint4 o;
                o.x = silu2h(hfma2v(aijh, wa.x, hfma2v(d2h, wd.x, hadd2v(pi.x, pj.x))));
                o.y = silu2h(hfma2v(aijh, wa.y, hfma2v(d2h, wd.y, hadd2v(pi.y, pj.y))));
                o.z = silu2h(hfma2v(aijh, wa.z, hfma2v(d2h, wd.z, hadd2v(pi.z, pj.z))));
                o.w = silu2h(hfma2v(aijh, wa.w, hfma2v(d2h, wd.w, hadd2v(pi.w, pj.w))));
                trow[k8] = o;
            }
            __syncwarp();

            // ---- gemm1: m_pre = T @ We2 + be2 (fp16 accum, bias in C) ----
            uint32_t acc[2][8][2];
            do_gemm(Wf2, biash2, acc, a_addr, t4, lane);
            __syncwarp();

            // ---- epilogue1: m = silu(D) (already half2); macc; Ts <- m ----
#pragma unroll
            for (int mt = 0; mt < 2; mt++) {
                const int e0 = wrow + mt * 16 + g;
                const int e1 = e0 + 8;
                const bool d0 = (jb + e0) == i;
                const bool d1 = (jb + e1) == i;
#pragma unroll
                for (int nt = 0; nt < 8; nt++) {
                    uint32_t h0 = silu2h(acc[mt][nt][0]);
                    uint32_t h1 = silu2h(acc[mt][nt][1]);
                    float2 f0 = uph2(h0);
                    float2 f1 = uph2(h1);
                    if (!d0) { macc[nt*2] += f0.x; macc[nt*2+1] += f0.y; }
                    if (!d1) { macc[nt*2] += f1.x; macc[nt*2+1] += f1.y; }
                    Ts[e0 * TS36 + nt * 4 + t4] = h0;
                    Ts[e1 * TS36 + nt * 4 + t4] = h1;
                }
            }
            __syncwarp();

            // ---- gemm2: u_pre = M @ Wx1 + bx1 (fp16 accum) ----
            do_gemm(Wf1, biash1, acc, a_addr, t4, lane);

            // ---- epilogue2: s = silu(u) . Wx2 + bx2 (half2 dot) ----
            uint32_t se0a = 0, se1a = 0, se0b = 0, se1b = 0;
#pragma unroll
            for (int np = 0; np < 4; np++) {
#pragma unroll
                for (int mt = 0; mt < 2; mt++) {
                    uint32_t u0 = silu2h(acc[mt][2*np][0]);
                    uint32_t u1 = silu2h(acc[mt][2*np][1]);
                    uint32_t v0 = silu2h(acc[mt][2*np+1][0]);
                    uint32_t v1 = silu2h(acc[mt][2*np+1][1]);
                    if (mt == 0) {
                        se0a = hfma2v(u0, wxh[np][0], se0a);
                        se0a = hfma2v(v0, wxh[np][1], se0a);
                        se1a = hfma2v(u1, wxh[np][0], se1a);
                        se1a = hfma2v(v1, wxh[np][1], se1a);
                    } else {
                        se0b = hfma2v(u0, wxh[np][0], se0b);
                        se0b = hfma2v(v0, wxh[np][1], se0b);
                        se1b = hfma2v(u1, wxh[np][0], se1b);
                        se1b = hfma2v(v1, wxh[np][1], se1b);
                    }
                }
            }
            float2 fr;
            fr = uph2(se0a); float sp0 = fr.x + fr.y;
            fr = uph2(se1a); float sp1 = fr.x + fr.y;
            fr = uph2(se0b); float sp2 = fr.x + fr.y;
            fr = uph2(se1b); float sp3 = fr.x + fr.y;

            sp0 += __shfl_xor_sync(0xffffffffu, sp0, 1);
            sp0 += __shfl_xor_sync(0xffffffffu, sp0, 2);
            sp1 += __shfl_xor_sync(0xffffffffu, sp1, 1);
            sp1 += __shfl_xor_sync(0xffffffffu, sp1, 2);
            sp2 += __shfl_xor_sync(0xffffffffu, sp2, 1);
            sp2 += __shfl_xor_sync(0xffffffffu, sp2, 2);
            sp3 += __shfl_xor_sync(0xffffffffu, sp3, 1);
            sp3 += __shfl_xor_sync(0xffffffffu, sp3, 2);
            if (t4 == 0) {
                s_sh[wrow + g]      = sp0 + bx2v;
                s_sh[wrow + 8 + g]  = sp1 + bx2v;
                s_sh[wrow + 16 + g] = sp2 + bx2v;
                s_sh[wrow + 24 + g] = sp3 + bx2v;
            }
            __syncwarp();

            // ---- phase 4: coordinate accumulation ----
            float s = s_sh[tid];
            if (j != i) {
                xa0 = fmaf(dx0, s, xa0);
                xa1 = fmaf(dx1, s, xa1);
                xa2 = fmaf(dx2, s, xa2);
            }
        }

        // ---- macc: reduce over g within warp, write per-warp partials ----
#pragma unroll
        for (int q = 0; q < 16; q++) {
            macc[q] += __shfl_xor_sync(0xffffffffu, macc[q], 4);
            macc[q] += __shfl_xor_sync(0xffffffffu, macc[q], 8);
            macc[q] += __shfl_xor_sync(0xffffffffu, macc[q], 16);
        }
        if (lane < 4) {
#pragma unroll
            for (int nt = 0; nt < 8; nt++) {
                mired[warp * 64 + nt * 8 + lane * 2]     = macc[nt * 2];
                mired[warp * 64 + nt * 8 + lane * 2 + 1] = macc[nt * 2 + 1];
            }
        }
#pragma unroll
        for (int o = 16; o >= 1; o >>= 1) {
            xa0 += __shfl_xor_sync(0xffffffffu, xa0, o);
            xa1 += __shfl_xor_sync(0xffffffffu, xa1, o);
            xa2 += __shfl_xor_sync(0xffffffffu, xa2, o);
        }
        if (lane == 0) {
            xred[warp * 3 + 0] = xa0;
            xred[warp * 3 + 1] = xa1;
            xred[warp * 3 + 2] = xa2;
        }
        __syncthreads();

        if (tid < 64) {
            float s = 0.f;
#pragma unroll
            for (int w = 0; w < 16; w++) s += mired[w * 64 + tid];
            mi_s[tid] = s;
        }
        if (tid < 3) {
            float s = 0.f;
#pragma unroll
            for (int w = 0; w < 16; w++) s += xred[w * 3 + tid];
            out[i * 3 + tid] = fmaf(C, s, xs[i * 3 + tid]);
        }
        __syncthreads();

        // ---- h_new: 2-layer MLP (weights from SMEM) ----
        if (tid < 256) {
            const int c = tid & 63, p = tid >> 6;
            float a1 = 0.f;
            if (p < 2) {
                const float* hr = his + p * 32;
                const float* wr = Wh1s + (p * 32) * 64 + c;
#pragma unroll 8
                for (int q = 0; q < 32; q++) a1 = fmaf(hr[q], wr[q * 64], a1);
            } else {
                const float* mr = mi_s + (p - 2) * 32;
                const float* wr = Wh1s + (64 + (p - 2) * 32) * 64 + c;
#pragma unroll 8
                for (int q = 0; q < 32; q++) a1 = fmaf(mr[q], wr[q * 64], a1);
            }
            s_sh[tid] = a1;
        }
        __syncthreads();
        if (tid < 64)
            hids[tid] = silu_t(bh1s[tid] + s_sh[tid] + s_sh[64 + tid] +
                               s_sh[128 + tid] + s_sh[192 + tid]);
        __syncthreads();
        if (tid < 256) {
            const int c = tid & 63, p = tid >> 6;
            float a2 = 0.f;
            const float* hp = hids + p * 16;
            const float* wr = Wh2s + (p * 16) * 64 + c;
#pragma unroll 8
            for (int q = 0; q < 16; q++) a2 = fmaf(hp[q], wr[q * 64], a2);
            s_sh[tid] = a2;
        }
        __syncthreads();
        if (tid < 64)
            out[3 * M_NODES + i * 64 + tid] =
                bh2s[tid] + s_sh[tid] + s_sh[64 + tid] + s_sh[128 + tid] + s_sh[192 + tid];
    }
}

extern "C" void kernel_launch(void* const* d_in, const int* in_sizes, int n_in,
                              void* d_out, int out_size) {
    const float* x   = (const float*)d_in[0];
    const float* a   = (const float*)d_in[1];
    const float* h   = (const float*)d_in[2];
    const float* We1 = (const float*)d_in[3];
    const float* be1 = (const float*)d_in[4];
    const float* We2 = (const float*)d_in[5];
    const float* be2 = (const float*)d_in[6];
    const float* Wx1 = (const float*)d_in[7];
    const float* bx1 = (const float*)d_in[8];
    const float* Wx2 = (const float*)d_in[9];
    const float* bx2 = (const float*)d_in[10];
    const float* Wh1 = (const float*)d_in[11];
    const float* bh1 = (const float*)d_in[12];
    const float* Wh2 = (const float*)d_in[13];
    const float* bh2 = (const float*)d_in[14];
    float* out = (float*)d_out;

    cudaFuncSetAttribute(ecnn_main, cudaFuncAttributeMaxDynamicSharedMemorySize,
                         SMEM_BYTES);

    prep_kernel<<<(M_NODES * 64) / 256, 256>>>(h, We1, be1);
    ecnn_main<<<NBLK, NTH, SMEM_BYTES>>>(
        x, a, h, We1, We2, be2, Wx1, bx1, Wx2, bx2, Wh1, bh1, Wh2, bh2, out);
}